// round 4
// baseline (speedup 1.0000x reference)
#include <cuda_runtime.h>
#include <math.h>

#define NB 2048

typedef unsigned int       u32;
typedef unsigned long long u64;

// ---------------- static device scratch ----------------
__device__ float g_bufM[7356416];      // float conv/pool outputs (max 2048*8*449)
__device__ u64   g_bufP[919552];       // packed activations (max 2048*449 words)
__device__ float g_scales[320];        // per-channel weight scales, layers 2-7
__device__ double g_psd1[16384];       // block1 stat partials [8][2048]
__device__ double g_psd2[16384];
__device__ long long g_psl1[16384];    // int stat partials (max 32*432=13824)
__device__ long long g_psl2[16384];
__device__ float g_bna[80];
__device__ float g_bnc[80];
__device__ int   g_ctr[8];             // zero-init; each conv resets its slot

__device__ __forceinline__ int popc_w(u32 x) { return __popc(x); }
__device__ __forceinline__ int popc_w(u64 x) { return __popcll(x); }

// =============== block 1: tiled fp32 conv + maxpool + stats (one CTA per image) ===============
// k16 s2 p7, pool 8/4, LIN=3600 -> conv 1800 -> pool 449, CO=8
__global__ void __launch_bounds__(256) conv1_kernel(
    const float* __restrict__ x, const float* __restrict__ w1,
    const float* __restrict__ gamma, const float* __restrict__ beta,
    float* __restrict__ out,
    double* __restrict__ ps1, double* __restrict__ ps2,
    float* __restrict__ bna, float* __restrict__ bnc, int* __restrict__ ctr)
{
    constexpr int LIN = 3600, LC = 1800, LP = 449, CO = 8, K = 16;
    extern __shared__ float sm[];
    float* sx    = sm;            // [3614] padded input
    float* sconv = sm + 3614;     // [8][1800]
    float* sw    = sm + 3614 + 14400; // [128]

    const int tid = threadIdx.x;
    const int n   = blockIdx.x;

    // padded input
    if (tid < 7) { sx[tid] = 0.f; sx[3607 + tid] = 0.f; }
    const float* __restrict__ xp = x + (size_t)n * LIN;
    for (int i = tid; i < LIN; i += 256) sx[7 + i] = xp[i];

    // binarize weights in-block (deterministic serial order per channel)
    if (tid < CO) {
        const float* wr = w1 + tid * K;
        double sd = 0.0;
        for (int k = 0; k < K; k++) sd += (double)fabsf(wr[k]);
        float sc = (float)(sd / (double)K);
        for (int k = 0; k < K; k++) {
            float v = wr[k];
            sw[tid * K + k] = (v > 0.f) ? sc : ((v < 0.f) ? -sc : 0.f);
        }
    }
    __syncthreads();

    // stage 1: each conv output computed once. thread handles 4 consecutive positions.
#pragma unroll
    for (int it = 0; it < 2; it++) {
        int cp0 = (it * 256 + tid) * 4;
        if (cp0 < LC) {
            float win[22];
#pragma unroll
            for (int t = 0; t < 22; t++) win[t] = sx[2 * cp0 + t];
#pragma unroll
            for (int c = 0; c < CO; c++) {
                float a0 = 0.f, a1 = 0.f, a2 = 0.f, a3 = 0.f;
#pragma unroll
                for (int k = 0; k < K; k++) {
                    float wv = sw[c * K + k];
                    a0 = fmaf(win[k],     wv, a0);
                    a1 = fmaf(win[k + 2], wv, a1);
                    a2 = fmaf(win[k + 4], wv, a2);
                    a3 = fmaf(win[k + 6], wv, a3);
                }
                sconv[c * LC + cp0]     = a0;
                sconv[c * LC + cp0 + 1] = a1;
                sconv[c * LC + cp0 + 2] = a2;
                sconv[c * LC + cp0 + 3] = a3;
            }
        }
    }
    __syncthreads();

    // stage 2: pooling + per-image stat partials. warp w = channel w.
    const int lane = tid & 31, wid = tid >> 5;
    double d1 = 0.0, d2 = 0.0;
    for (int lp = lane; lp < LP; lp += 32) {
        const float* cb = sconv + wid * LC + lp * 4;
        float m = cb[0];
#pragma unroll
        for (int j = 1; j < 8; j++) m = fmaxf(m, cb[j]);
        out[((size_t)n * CO + wid) * LP + lp] = m;
        d1 += (double)m;
        d2 += (double)m * (double)m;
    }
#pragma unroll
    for (int off = 16; off > 0; off >>= 1) {
        d1 += __shfl_down_sync(0xFFFFFFFFu, d1, off);
        d2 += __shfl_down_sync(0xFFFFFFFFu, d2, off);
    }
    if (lane == 0) { ps1[wid * NB + n] = d1; ps2[wid * NB + n] = d2; }

    // last-block finalize
    __shared__ int sLast;
    __syncthreads();
    if (tid == 0) {
        __threadfence();
        int old = atomicAdd(ctr, 1);
        sLast = (old == (int)gridDim.x - 1);
    }
    __syncthreads();
    if (sLast) {
        double t1 = 0.0, t2 = 0.0;
        for (int i = lane; i < NB; i += 32) { t1 += ps1[wid * NB + i]; t2 += ps2[wid * NB + i]; }
#pragma unroll
        for (int off = 16; off > 0; off >>= 1) {
            t1 += __shfl_down_sync(0xFFFFFFFFu, t1, off);
            t2 += __shfl_down_sync(0xFFFFFFFFu, t2, off);
        }
        if (lane == 0) {
            const double invcnt = 1.0 / (2048.0 * 449.0);
            double m = t1 * invcnt;
            double v = t2 * invcnt - m * m;
            if (v < 0.0) v = 0.0;
            double a = (double)gamma[wid] / sqrt(v + 1e-5);
            bna[wid] = (float)a;
            bnc[wid] = (float)((double)beta[wid] - m * a);
        }
        __syncthreads();
        if (tid == 0) *ctr = 0;
    }
}

// =============== XNOR-popcount conv + maxpool + exact int stats + finalize ===============
template <typename WT, int CIN, int COUT, int CO_T, int K, int STR, int PAD, int PK, int PS, int LIN, int LP>
__global__ void __launch_bounds__(256) conv_popc_kernel(
    const WT* __restrict__ inP, float* __restrict__ out,
    const float* __restrict__ wraw, float* __restrict__ scales,
    const float* __restrict__ gamma, const float* __restrict__ beta,
    long long* __restrict__ ps1, long long* __restrict__ ps2,
    float* __restrict__ bna, float* __restrict__ bnc,
    int* __restrict__ ctr, double invcnt)
{
    constexpr int WREAL = (PK - 1) * STR + K;
    constexpr WT  MCIN  = (CIN >= (int)(8 * sizeof(WT))) ? (WT)~(WT)0 : (WT)(((WT)1 << CIN) - 1);

    __shared__ WT sw[CO_T * K];
    __shared__ float ssc[CO_T];
    const int cob = blockIdx.y * CO_T;
    const int tid = threadIdx.x;

    // binarize + pack this block's channels (deterministic serial per channel)
    if (tid < CO_T) {
        const int o = cob + tid;
        const float* wr = wraw + (size_t)o * CIN * K;
        double sd = 0.0;
        for (int i = 0; i < CIN * K; i++) sd += (double)fabsf(wr[i]);
        float sc = (float)(sd / (double)(CIN * K));
        ssc[tid] = sc;
        scales[o] = sc;
        for (int k = 0; k < K; k++) {
            WT word = 0;
            for (int ci = 0; ci < CIN; ci++)
                if (wr[ci * K + k] > 0.f) word |= ((WT)1 << ci);
            sw[tid * K + k] = word;
        }
    }
    __syncthreads();

    const int idx = blockIdx.x * 256 + tid;          // exact grid
    const int n = idx / LP, lp = idx - n * LP;
    const int base0 = lp * PS * STR - PAD;
    const WT* __restrict__ ib = inP + (size_t)n * LIN;

    WT win[WREAL], msk[WREAL];
    int cnt[PK];
#pragma unroll
    for (int t = 0; t < WREAL; t++) {
        int p = base0 + t;
        bool v = (p >= 0 && p < LIN);
        win[t] = v ? ib[p] : (WT)0;
        msk[t] = v ? MCIN : (WT)0;
    }
#pragma unroll
    for (int j = 0; j < PK; j++) {
        int cc = 0;
#pragma unroll
        for (int k = 0; k < K; k++) cc += (msk[j * STR + k] != 0) ? CIN : 0;
        cnt[j] = cc;
    }

    int P[CO_T][PK];
#pragma unroll
    for (int c = 0; c < CO_T; c++)
#pragma unroll
        for (int j = 0; j < PK; j++) P[c][j] = 0;

#pragma unroll
    for (int k = 0; k < K; k++) {
#pragma unroll
        for (int c = 0; c < CO_T; c++) {
            WT wk = sw[c * K + k];
#pragma unroll
            for (int j = 0; j < PK; j++) {
                int t = j * STR + k;
                P[c][j] += popc_w((WT)(~(win[t] ^ wk) & msk[t]));
            }
        }
    }

    __shared__ int sh1[8][CO_T];
    __shared__ int sh2[8][CO_T];
    const int lane = tid & 31, wid = tid >> 5;
#pragma unroll
    for (int c = 0; c < CO_T; c++) {
        int mS = 2 * P[c][0] - cnt[0];
#pragma unroll
        for (int j = 1; j < PK; j++) {
            int s = 2 * P[c][j] - cnt[j];
            mS = (s > mS) ? s : mS;
        }
        out[((size_t)n * COUT + cob + c) * LP + lp] = ssc[c] * (float)mS;
        int v1 = mS, v2 = mS * mS;
#pragma unroll
        for (int off = 16; off > 0; off >>= 1) {
            v1 += __shfl_down_sync(0xFFFFFFFFu, v1, off);
            v2 += __shfl_down_sync(0xFFFFFFFFu, v2, off);
        }
        if (lane == 0) { sh1[wid][c] = v1; sh2[wid][c] = v2; }
    }
    __syncthreads();
    const int GX = gridDim.x;
    if (tid < CO_T) {
        long long t1 = 0, t2 = 0;
#pragma unroll
        for (int q = 0; q < 8; q++) { t1 += sh1[q][tid]; t2 += sh2[q][tid]; }
        ps1[(size_t)(cob + tid) * GX + blockIdx.x] = t1;
        ps2[(size_t)(cob + tid) * GX + blockIdx.x] = t2;
    }

    // last-block finalize: per-channel exact int sums -> BN coefs
    __shared__ int sLast;
    __syncthreads();
    if (tid == 0) {
        __threadfence();
        int old = atomicAdd(ctr, 1);
        sLast = (old == (int)(gridDim.x * gridDim.y) - 1);
    }
    __syncthreads();
    if (sLast) {
        for (int ch = wid; ch < COUT; ch += 8) {
            long long t1 = 0, t2 = 0;
            for (int i = lane; i < GX; i += 32) {
                t1 += ps1[(size_t)ch * GX + i];
                t2 += ps2[(size_t)ch * GX + i];
            }
#pragma unroll
            for (int off = 16; off > 0; off >>= 1) {
                t1 += __shfl_down_sync(0xFFFFFFFFu, t1, off);
                t2 += __shfl_down_sync(0xFFFFFFFFu, t2, off);
            }
            if (lane == 0) {
                double sc = (double)scales[ch];
                double m  = sc * (double)t1 * invcnt;
                double e2 = sc * sc * (double)t2 * invcnt;
                double v  = e2 - m * m;
                if (v < 0.0) v = 0.0;
                double a = (double)gamma[ch] / sqrt(v + 1e-5);
                bna[ch] = (float)a;
                bnc[ch] = (float)((double)beta[ch] - m * a);
            }
        }
        __syncthreads();
        if (tid == 0) *ctr = 0;
    }
}

// =============== BN + sign + channel-pack ===============
template <typename WT, int C, int LP>
__global__ void __launch_bounds__(256) pack_kernel(
    const float* __restrict__ m, const float* __restrict__ a, const float* __restrict__ c,
    WT* __restrict__ outP)
{
    __shared__ float sa[C], sc[C];
    if (threadIdx.x < C) { sa[threadIdx.x] = a[threadIdx.x]; sc[threadIdx.x] = c[threadIdx.x]; }
    __syncthreads();
    const int idx = blockIdx.x * 256 + threadIdx.x;   // exact grid
    const int n = idx / LP, lp = idx - n * LP;
    WT word = 0;
#pragma unroll
    for (int co = 0; co < C; co++) {
        float v = fmaf(sa[co], m[((size_t)n * C + co) * LP + lp], sc[co]);
        if (v > 0.f) word |= ((WT)1 << co);
    }
    outP[(size_t)n * LP + lp] = word;
}

// =============== FC with fused wfc binarization + block-7 BN+sign ===============
__global__ void fc_bn_kernel(const float* __restrict__ m7, const float* __restrict__ wfc,
                             const float* __restrict__ a, const float* __restrict__ c,
                             float* __restrict__ out)
{
    __shared__ float swfc[1080];
    __shared__ float sa[72], sc[72];
    __shared__ float sscale[5];
    const int tid = threadIdx.x;
    if (tid < 5) {
        double sd = 0.0;
        for (int i = 0; i < 216; i++) sd += (double)fabsf(wfc[tid * 216 + i]);
        sscale[tid] = (float)(sd / 216.0);
    }
    if (tid < 72) { sa[tid] = a[tid]; sc[tid] = c[tid]; }
    __syncthreads();
    for (int i = tid; i < 1080; i += 256) {
        float v = wfc[i];
        float s = sscale[i / 216];
        swfc[i] = (v > 0.f) ? s : ((v < 0.f) ? -s : 0.f);
    }
    __syncthreads();

    const int idx = blockIdx.x * 256 + tid;
    if (idx >= NB * 5) return;
    const int n = idx / 5, j = idx - n * 5;
    const float* __restrict__ mb = m7 + (size_t)n * 216;
    const float* __restrict__ wb = swfc + j * 216;
    float s = 0.f;
#pragma unroll 4
    for (int co = 0; co < 72; co++) {
        float av = sa[co], cv = sc[co];
#pragma unroll
        for (int l = 0; l < 3; l++) {
            float v = fmaf(av, mb[co * 3 + l], cv);
            float sg = (v > 0.f) ? 1.f : ((v < 0.f) ? -1.f : 0.f);
            s = fmaf(sg, wb[co * 3 + l], s);
        }
    }
    out[n * 5 + j] = s;
}

// ---------------- launch ----------------
extern "C" void kernel_launch(void* const* d_in, const int* in_sizes, int n_in,
                              void* d_out, int out_size)
{
    const float* x = (const float*)d_in[0];
    const float* w[7]; const float* g[7]; const float* b[7];
    const bool interleaved = (in_sizes[2] == 8);
    for (int i = 0; i < 7; i++) {
        if (interleaved) {
            w[i] = (const float*)d_in[1 + 3 * i];
            g[i] = (const float*)d_in[2 + 3 * i];
            b[i] = (const float*)d_in[3 + 3 * i];
        } else {
            w[i] = (const float*)d_in[1 + i];
            g[i] = (const float*)d_in[8 + i];
            b[i] = (const float*)d_in[15 + i];
        }
    }
    const float* wfc = (const float*)d_in[22];
    float* out = (float*)d_out;

    float *bufM, *scales, *bna, *bnc;
    u64 *bufP;
    double *psd1, *psd2;
    long long *psl1, *psl2;
    int *ctr;
    cudaGetSymbolAddress((void**)&bufM, g_bufM);
    cudaGetSymbolAddress((void**)&bufP, g_bufP);
    cudaGetSymbolAddress((void**)&scales, g_scales);
    cudaGetSymbolAddress((void**)&psd1, g_psd1);
    cudaGetSymbolAddress((void**)&psd2, g_psd2);
    cudaGetSymbolAddress((void**)&psl1, g_psl1);
    cudaGetSymbolAddress((void**)&psl2, g_psl2);
    cudaGetSymbolAddress((void**)&bna, g_bna);
    cudaGetSymbolAddress((void**)&bnc, g_bnc);
    cudaGetSymbolAddress((void**)&ctr, g_ctr);

    u32* bufP32 = (u32*)bufP;

    // block 1: tiled fp32, 72.6KB dynamic smem
    const int smem1 = (3614 + 14400 + 128) * 4;
    cudaFuncSetAttribute(conv1_kernel, cudaFuncAttributeMaxDynamicSharedMemorySize, smem1);
    conv1_kernel<<<NB, 256, smem1>>>(x, w[0], g[0], b[0], bufM, psd1, psd2, bna, bnc, ctr + 0);
    pack_kernel<u32, 8, 449><<<3592, 256>>>(bufM, bna, bnc, bufP32);

    // block 2: 8->12, k12 s2 p5, pool 4/2, 449->111
    conv_popc_kernel<u32, 8, 12, 12, 12, 2, 5, 4, 2, 449, 111>
        <<<dim3(888, 1), 256>>>(bufP32, bufM, w[1], scales + 0, g[1], b[1],
                                psl1, psl2, bna, bnc, ctr + 1, 1.0 / (2048.0 * 111.0));
    pack_kernel<u32, 12, 111><<<888, 256>>>(bufM, bna, bnc, bufP32);

    // block 3: 12->32, k9 s1 p4, pool 5/2, 111->54
    conv_popc_kernel<u32, 12, 32, 16, 9, 1, 4, 5, 2, 111, 54>
        <<<dim3(432, 2), 256>>>(bufP32, bufM, w[2], scales + 12, g[2], b[2],
                                psl1, psl2, bna, bnc, ctr + 2, 1.0 / (2048.0 * 54.0));
    pack_kernel<u32, 32, 54><<<432, 256>>>(bufM, bna, bnc, bufP32);

    // block 4: 32->64, k7 s1 p3, pool 4/2, 54->26
    conv_popc_kernel<u32, 32, 64, 16, 7, 1, 3, 4, 2, 54, 26>
        <<<dim3(208, 4), 256>>>(bufP32, bufM, w[3], scales + 44, g[3], b[3],
                                psl1, psl2, bna, bnc, ctr + 3, 1.0 / (2048.0 * 26.0));
    pack_kernel<u64, 64, 26><<<208, 256>>>(bufM, bna, bnc, bufP);

    // block 5: 64->64, k5 s1 p2, pool 2/2, 26->13
    conv_popc_kernel<u64, 64, 64, 16, 5, 1, 2, 2, 2, 26, 13>
        <<<dim3(104, 4), 256>>>(bufP, bufM, w[4], scales + 108, g[4], b[4],
                                psl1, psl2, bna, bnc, ctr + 4, 1.0 / (2048.0 * 13.0));
    pack_kernel<u64, 64, 13><<<104, 256>>>(bufM, bna, bnc, bufP);

    // block 6: 64->64, k3 s1 p1, pool 2/2, 13->6
    conv_popc_kernel<u64, 64, 64, 16, 3, 1, 1, 2, 2, 13, 6>
        <<<dim3(48, 4), 256>>>(bufP, bufM, w[5], scales + 172, g[5], b[5],
                                psl1, psl2, bna, bnc, ctr + 5, 1.0 / (2048.0 * 6.0));
    pack_kernel<u64, 64, 6><<<48, 256>>>(bufM, bna, bnc, bufP);

    // block 7: 64->72, k3 s1 p1, pool 2/2, 6->3
    conv_popc_kernel<u64, 64, 72, 24, 3, 1, 1, 2, 2, 6, 3>
        <<<dim3(24, 3), 256>>>(bufP, bufM, w[6], scales + 236, g[6], b[6],
                               psl1, psl2, bna, bnc, ctr + 6, 1.0 / (2048.0 * 3.0));

    // FC with fused BN+sign: [2048,216] @ [5,216]^T
    fc_bn_kernel<<<(NB * 5 + 255) / 256, 256>>>(bufM, wfc, bna, bnc, out);
}

// round 5
// speedup vs baseline: 3.0249x; 3.0249x over previous
#include <cuda_runtime.h>
#include <math.h>

#define NB 2048

typedef unsigned int       u32;
typedef unsigned long long u64;

// ---------------- static device scratch ----------------
__device__ float g_bufM[7356416];      // float conv/pool outputs (max 2048*8*449)
__device__ u64   g_bufP[919552];       // packed activations (max 2048*449 words)
__device__ float g_bw1[128];           // block1 binarized weights (8*16)
__device__ float g_bwfc[1080];         // FC binarized weights (5*216)
__device__ u32   g_wp2[144];           // 12*12
__device__ u32   g_wp3[288];           // 32*9
__device__ u32   g_wp4[448];           // 64*7
__device__ u64   g_wp5[320];           // 64*5
__device__ u64   g_wp6[192];           // 64*3
__device__ u64   g_wp7[216];           // 72*3
__device__ float g_scales[320];        // per-channel weight scales, layers 2-7
__device__ double g_psd1[14400];       // block1 stat partials [8][1800]
__device__ double g_psd2[14400];
__device__ u64   g_sS1[320];           // exact int stat slots, layers 2-7 (offsets as scales)
__device__ u64   g_sS2[320];
__device__ float g_bna[16];            // block1 BN coefs
__device__ float g_bnc[16];

__device__ __forceinline__ int popc_w(u32 x) { return __popc(x); }
__device__ __forceinline__ int popc_w(u64 x) { return __popcll(x); }

// ---------------- all weight binarization in ONE kernel ----------------
__global__ void binw_all_kernel(
    const float* w1, const float* w2, const float* w3, const float* w4,
    const float* w5, const float* w6, const float* w7, const float* wfc,
    float* bw1, u32* wp2, u32* wp3, u32* wp4, u64* wp5, u64* wp6, u64* wp7,
    float* bwfc, float* scales)
{
    const int starts[9] = {0, 8, 20, 52, 116, 180, 244, 316, 321};
    const int CINs[8]   = {1, 8, 12, 32, 64, 64, 64, 216};
    const int Ks[8]     = {16, 12, 9, 7, 5, 3, 3, 1};
    const int soff[8]   = {0, 0, 12, 44, 108, 172, 236, 0};
    const float* ws[8]  = {w1, w2, w3, w4, w5, w6, w7, wfc};

    const int bx = blockIdx.x;
    int layer = 0;
    while (bx >= starts[layer + 1]) layer++;
    const int o   = bx - starts[layer];
    const int CIN = CINs[layer], K = Ks[layer], IK = CIN * K;
    const float* wrow = ws[layer] + o * IK;
    const int tid = threadIdx.x;

    __shared__ double sd[64];
    double acc = 0.0;
    for (int i = tid; i < IK; i += 64) acc += (double)fabsf(wrow[i]);
    sd[tid] = acc;
    __syncthreads();
    for (int s = 32; s > 0; s >>= 1) {
        if (tid < s) sd[tid] += sd[tid + s];
        __syncthreads();
    }
    const float scale = (float)(sd[0] / (double)IK);

    if (layer == 0) {
        for (int i = tid; i < IK; i += 64) {
            float v = wrow[i];
            bw1[o * IK + i] = (v > 0.f) ? scale : ((v < 0.f) ? -scale : 0.f);
        }
    } else if (layer == 7) {
        for (int i = tid; i < IK; i += 64) {
            float v = wrow[i];
            bwfc[o * IK + i] = (v > 0.f) ? scale : ((v < 0.f) ? -scale : 0.f);
        }
    } else {
        if (tid == 0) scales[soff[layer] + o] = scale;
        if (layer <= 3) {
            u32* wp = (layer == 1) ? wp2 : (layer == 2) ? wp3 : wp4;
            for (int k = tid; k < K; k += 64) {
                u32 word = 0;
                for (int ci = 0; ci < CIN; ci++)
                    if (wrow[ci * K + k] > 0.f) word |= (1u << ci);
                wp[o * K + k] = word;
            }
        } else {
            u64* wp = (layer == 4) ? wp5 : (layer == 5) ? wp6 : wp7;
            for (int k = tid; k < K; k += 64) {
                u64 word = 0;
                for (int ci = 0; ci < CIN; ci++)
                    if (wrow[ci * K + k] > 0.f) word |= (1ull << ci);
                wp[o * K + k] = word;
            }
        }
    }
}

// =============== block 1: fp32 conv + maxpool, 2 pool outputs per thread ===============
// k16 s2 p7, pool 8/4, LIN=3600, LP=449, CO=8. grid = 2048*225/256 = 1800 exact.
__global__ void __launch_bounds__(256) conv1_kernel(
    const float* __restrict__ x, const float* __restrict__ bw,
    float* __restrict__ out, double* __restrict__ ps1, double* __restrict__ ps2)
{
    constexpr int LIN = 3600, LP = 449, CO = 8, K = 16;
    __shared__ float sw[CO * K];
    const int tid = threadIdx.x;
    if (tid < CO * K) sw[tid] = bw[tid];
    __syncthreads();

    const int idx  = blockIdx.x * 256 + tid;         // < 2048*225 exact
    const int n    = idx / 225;
    const int slot = idx - n * 225;
    const int lp0  = slot * 2;
    const bool v1  = (slot < 224);
    const int base0 = lp0 * 8 - 7;
    const float* __restrict__ xp = x + (size_t)n * LIN;

    float win[38];
#pragma unroll
    for (int t = 0; t < 38; t++) {
        int p = base0 + t;
        win[t] = (p >= 0 && p < LIN) ? xp[p] : 0.f;
    }

    __shared__ float sh1[8][CO], sh2[8][CO];
    const int lane = tid & 31, wid = tid >> 5;

#pragma unroll
    for (int c = 0; c < CO; c++) {
        float wv[K];
#pragma unroll
        for (int k = 0; k < K; k++) wv[k] = sw[c * K + k];
        float m0 = -1e30f, m1 = -1e30f;
#pragma unroll
        for (int r = 0; r < 12; r++) {
            float s = 0.f;
#pragma unroll
            for (int k = 0; k < K; k++) s = fmaf(win[2 * r + k], wv[k], s);
            if (r < 8) m0 = fmaxf(m0, s);
            if (r >= 4) m1 = fmaxf(m1, s);
        }
        out[((size_t)n * CO + c) * LP + lp0] = m0;
        if (v1) out[((size_t)n * CO + c) * LP + lp0 + 1] = m1;

        float a1 = m0 + (v1 ? m1 : 0.f);
        float a2 = m0 * m0 + (v1 ? m1 * m1 : 0.f);
#pragma unroll
        for (int off = 16; off > 0; off >>= 1) {
            a1 += __shfl_down_sync(0xFFFFFFFFu, a1, off);
            a2 += __shfl_down_sync(0xFFFFFFFFu, a2, off);
        }
        if (lane == 0) { sh1[wid][c] = a1; sh2[wid][c] = a2; }
    }
    __syncthreads();
    if (tid < CO) {
        double t1 = 0.0, t2 = 0.0;
#pragma unroll
        for (int q = 0; q < 8; q++) { t1 += (double)sh1[q][tid]; t2 += (double)sh2[q][tid]; }
        ps1[tid * 1800 + blockIdx.x] = t1;
        ps2[tid * 1800 + blockIdx.x] = t2;
    }
}

// =============== block1 BN finalize ===============
__global__ void stats_fin_d(const double* __restrict__ ps1, const double* __restrict__ ps2,
                            const float* __restrict__ gamma, const float* __restrict__ beta,
                            float* __restrict__ bna, float* __restrict__ bnc)
{
    const int ch = blockIdx.x, G = 1800;
    __shared__ double s1[256], s2[256];
    double a1 = 0.0, a2 = 0.0;
    for (int i = threadIdx.x; i < G; i += 256) { a1 += ps1[ch * G + i]; a2 += ps2[ch * G + i]; }
    s1[threadIdx.x] = a1; s2[threadIdx.x] = a2;
    __syncthreads();
    for (int s = 128; s > 0; s >>= 1) {
        if (threadIdx.x < s) { s1[threadIdx.x] += s1[threadIdx.x + s]; s2[threadIdx.x] += s2[threadIdx.x + s]; }
        __syncthreads();
    }
    if (threadIdx.x == 0) {
        const double invcnt = 1.0 / (2048.0 * 449.0);
        double m = s1[0] * invcnt;
        double v = s2[0] * invcnt - m * m;
        if (v < 0.0) v = 0.0;
        double a = (double)gamma[ch] / sqrt(v + 1e-5);
        bna[ch] = (float)a;
        bnc[ch] = (float)((double)beta[ch] - m * a);
    }
}

// =============== XNOR-popcount conv + maxpool + exact int stats via u64 atomics ===============
template <typename WT, int CIN, int COUT, int CO_T, int K, int STR, int PAD, int PK, int PS, int LIN, int LP>
__global__ void __launch_bounds__(256) conv_popc_kernel(
    const WT* __restrict__ inP, float* __restrict__ out,
    const WT* __restrict__ wp, const float* __restrict__ scales,
    u64* __restrict__ sS1, u64* __restrict__ sS2)
{
    constexpr int WREAL = (PK - 1) * STR + K;
    constexpr WT  MCIN  = (CIN >= (int)(8 * sizeof(WT))) ? (WT)~(WT)0 : (WT)(((WT)1 << CIN) - 1);

    __shared__ WT sw[CO_T * K];
    __shared__ float ssc[CO_T];
    const int cob = blockIdx.y * CO_T;
    const int tid = threadIdx.x;
    for (int i = tid; i < CO_T * K; i += 256) sw[i] = wp[cob * K + i];
    if (tid < CO_T) ssc[tid] = scales[cob + tid];
    __syncthreads();

    const int idx = blockIdx.x * 256 + tid;          // exact grid
    const int n = idx / LP, lp = idx - n * LP;
    const int base0 = lp * PS * STR - PAD;
    const WT* __restrict__ ib = inP + (size_t)n * LIN;

    WT win[WREAL], msk[WREAL];
    int cnt[PK];
#pragma unroll
    for (int t = 0; t < WREAL; t++) {
        int p = base0 + t;
        bool v = (p >= 0 && p < LIN);
        win[t] = v ? ib[p] : (WT)0;
        msk[t] = v ? MCIN : (WT)0;
    }
#pragma unroll
    for (int j = 0; j < PK; j++) {
        int cc = 0;
#pragma unroll
        for (int k = 0; k < K; k++) cc += (msk[j * STR + k] != 0) ? CIN : 0;
        cnt[j] = cc;
    }

    int P[CO_T][PK];
#pragma unroll
    for (int c = 0; c < CO_T; c++)
#pragma unroll
        for (int j = 0; j < PK; j++) P[c][j] = 0;

#pragma unroll
    for (int k = 0; k < K; k++) {
#pragma unroll
        for (int c = 0; c < CO_T; c++) {
            WT wk = sw[c * K + k];
#pragma unroll
            for (int j = 0; j < PK; j++) {
                int t = j * STR + k;
                P[c][j] += popc_w((WT)(~(win[t] ^ wk) & msk[t]));
            }
        }
    }

    __shared__ int sh1[8][CO_T];
    __shared__ int sh2[8][CO_T];
    const int lane = tid & 31, wid = tid >> 5;
#pragma unroll
    for (int c = 0; c < CO_T; c++) {
        int mS = 2 * P[c][0] - cnt[0];
#pragma unroll
        for (int j = 1; j < PK; j++) {
            int s = 2 * P[c][j] - cnt[j];
            mS = (s > mS) ? s : mS;
        }
        out[((size_t)n * COUT + cob + c) * LP + lp] = ssc[c] * (float)mS;
        int v1 = mS, v2 = mS * mS;
#pragma unroll
        for (int off = 16; off > 0; off >>= 1) {
            v1 += __shfl_down_sync(0xFFFFFFFFu, v1, off);
            v2 += __shfl_down_sync(0xFFFFFFFFu, v2, off);
        }
        if (lane == 0) { sh1[wid][c] = v1; sh2[wid][c] = v2; }
    }
    __syncthreads();
    if (tid < CO_T) {
        long long t1 = 0, t2 = 0;
#pragma unroll
        for (int q = 0; q < 8; q++) { t1 += sh1[q][tid]; t2 += sh2[q][tid]; }
        atomicAdd(&sS1[cob + tid], (u64)t1);   // exact int: order-independent
        atomicAdd(&sS2[cob + tid], (u64)t2);
    }
}

// =============== pack for block1 (uses bna/bnc) + zero next-layer slots ===============
__global__ void __launch_bounds__(256) pack1_kernel(
    const float* __restrict__ m, const float* __restrict__ a, const float* __restrict__ c,
    u32* __restrict__ outP, u64* __restrict__ z1, u64* __restrict__ z2)
{
    constexpr int C = 8, LP = 449;
    __shared__ float sa[C], sc[C];
    if (threadIdx.x < C) { sa[threadIdx.x] = a[threadIdx.x]; sc[threadIdx.x] = c[threadIdx.x]; }
    if (blockIdx.x == 0 && threadIdx.x < 12) { z1[threadIdx.x] = 0; z2[threadIdx.x] = 0; }
    __syncthreads();
    const int idx = blockIdx.x * 256 + threadIdx.x;
    const int n = idx / LP, lp = idx - n * LP;
    u32 word = 0;
#pragma unroll
    for (int co = 0; co < C; co++) {
        float v = fmaf(sa[co], m[((size_t)n * C + co) * LP + lp], sc[co]);
        if (v > 0.f) word |= (1u << co);
    }
    outP[(size_t)n * LP + lp] = word;
}

// =============== pack with in-CTA BN-coef recompute from int slots + zero next slots ===============
template <typename WT, int C, int LP>
__global__ void __launch_bounds__(256) pack_stats_kernel(
    const float* __restrict__ m,
    const u64* __restrict__ sS1, const u64* __restrict__ sS2,
    const float* __restrict__ scales,
    const float* __restrict__ gamma, const float* __restrict__ beta,
    double invcnt, WT* __restrict__ outP,
    u64* __restrict__ z1, u64* __restrict__ z2, int zcnt)
{
    __shared__ float sa[C], sc[C];
    if (threadIdx.x < C) {
        const int ch = threadIdx.x;
        double sl = (double)(long long)sS1[ch];
        double s2 = (double)(long long)sS2[ch];
        double scw = (double)scales[ch];
        double mm = scw * sl * invcnt;
        double e2 = scw * scw * s2 * invcnt;
        double v  = e2 - mm * mm;
        if (v < 0.0) v = 0.0;
        double a = (double)gamma[ch] / sqrt(v + 1e-5);
        sa[ch] = (float)a;
        sc[ch] = (float)((double)beta[ch] - mm * a);
    }
    if (blockIdx.x == 0 && threadIdx.x < zcnt) { z1[threadIdx.x] = 0; z2[threadIdx.x] = 0; }
    __syncthreads();
    const int idx = blockIdx.x * 256 + threadIdx.x;   // exact grid
    const int n = idx / LP, lp = idx - n * LP;
    WT word = 0;
#pragma unroll
    for (int co = 0; co < C; co++) {
        float v = fmaf(sa[co], m[((size_t)n * C + co) * LP + lp], sc[co]);
        if (v > 0.f) word |= ((WT)1 << co);
    }
    outP[(size_t)n * LP + lp] = word;
}

// =============== FC with in-CTA block7 BN-coef recompute ===============
__global__ void fc_bn_kernel(const float* __restrict__ m7, const float* __restrict__ bwfc,
                             const u64* __restrict__ sS1, const u64* __restrict__ sS2,
                             const float* __restrict__ scales,
                             const float* __restrict__ gamma, const float* __restrict__ beta,
                             float* __restrict__ out)
{
    __shared__ float sa[72], sc[72];
    const int tid = threadIdx.x;
    if (tid < 72) {
        const double invcnt = 1.0 / (2048.0 * 3.0);
        double sl = (double)(long long)sS1[tid];
        double s2 = (double)(long long)sS2[tid];
        double scw = (double)scales[tid];
        double mm = scw * sl * invcnt;
        double e2 = scw * scw * s2 * invcnt;
        double v  = e2 - mm * mm;
        if (v < 0.0) v = 0.0;
        double a = (double)gamma[tid] / sqrt(v + 1e-5);
        sa[tid] = (float)a;
        sc[tid] = (float)((double)beta[tid] - mm * a);
    }
    __syncthreads();

    const int idx = blockIdx.x * 256 + tid;
    if (idx >= NB * 5) return;
    const int n = idx / 5, j = idx - n * 5;
    const float* __restrict__ mb = m7 + (size_t)n * 216;
    const float* __restrict__ wb = bwfc + j * 216;
    float s = 0.f;
#pragma unroll 4
    for (int co = 0; co < 72; co++) {
        float av = sa[co], cv = sc[co];
#pragma unroll
        for (int l = 0; l < 3; l++) {
            float v = fmaf(av, mb[co * 3 + l], cv);
            float sg = (v > 0.f) ? 1.f : ((v < 0.f) ? -1.f : 0.f);
            s = fmaf(sg, wb[co * 3 + l], s);
        }
    }
    out[n * 5 + j] = s;
}

// ---------------- launch ----------------
extern "C" void kernel_launch(void* const* d_in, const int* in_sizes, int n_in,
                              void* d_out, int out_size)
{
    const float* x = (const float*)d_in[0];
    const float* w[7]; const float* g[7]; const float* b[7];
    const bool interleaved = (in_sizes[2] == 8);
    for (int i = 0; i < 7; i++) {
        if (interleaved) {
            w[i] = (const float*)d_in[1 + 3 * i];
            g[i] = (const float*)d_in[2 + 3 * i];
            b[i] = (const float*)d_in[3 + 3 * i];
        } else {
            w[i] = (const float*)d_in[1 + i];
            g[i] = (const float*)d_in[8 + i];
            b[i] = (const float*)d_in[15 + i];
        }
    }
    const float* wfc = (const float*)d_in[22];
    float* out = (float*)d_out;

    float *bufM, *bw1, *bwfc, *scales, *bna, *bnc;
    u64 *bufP, *wp5, *wp6, *wp7, *sS1, *sS2;
    u32 *wp2, *wp3, *wp4;
    double *psd1, *psd2;
    cudaGetSymbolAddress((void**)&bufM, g_bufM);
    cudaGetSymbolAddress((void**)&bufP, g_bufP);
    cudaGetSymbolAddress((void**)&bw1, g_bw1);
    cudaGetSymbolAddress((void**)&bwfc, g_bwfc);
    cudaGetSymbolAddress((void**)&wp2, g_wp2);
    cudaGetSymbolAddress((void**)&wp3, g_wp3);
    cudaGetSymbolAddress((void**)&wp4, g_wp4);
    cudaGetSymbolAddress((void**)&wp5, g_wp5);
    cudaGetSymbolAddress((void**)&wp6, g_wp6);
    cudaGetSymbolAddress((void**)&wp7, g_wp7);
    cudaGetSymbolAddress((void**)&scales, g_scales);
    cudaGetSymbolAddress((void**)&psd1, g_psd1);
    cudaGetSymbolAddress((void**)&psd2, g_psd2);
    cudaGetSymbolAddress((void**)&sS1, g_sS1);
    cudaGetSymbolAddress((void**)&sS2, g_sS2);
    cudaGetSymbolAddress((void**)&bna, g_bna);
    cudaGetSymbolAddress((void**)&bnc, g_bnc);

    u32* bufP32 = (u32*)bufP;

    binw_all_kernel<<<321, 64>>>(w[0], w[1], w[2], w[3], w[4], w[5], w[6], wfc,
                                 bw1, wp2, wp3, wp4, wp5, wp6, wp7, bwfc, scales);

    // block 1: fp32 conv+pool (2 outputs/thread), stats, pack (+zero block2 slots)
    conv1_kernel<<<1800, 256>>>(x, bw1, bufM, psd1, psd2);
    stats_fin_d<<<8, 256>>>(psd1, psd2, g[0], b[0], bna, bnc);
    pack1_kernel<<<3592, 256>>>(bufM, bna, bnc, bufP32, sS1 + 0, sS2 + 0);

    // block 2: 8->12, k12 s2 p5, pool 4/2, 449->111
    conv_popc_kernel<u32, 8, 12, 12, 12, 2, 5, 4, 2, 449, 111>
        <<<dim3(888, 1), 256>>>(bufP32, bufM, wp2, scales + 0, sS1 + 0, sS2 + 0);
    pack_stats_kernel<u32, 12, 111><<<888, 256>>>(bufM, sS1 + 0, sS2 + 0, scales + 0,
        g[1], b[1], 1.0 / (2048.0 * 111.0), bufP32, sS1 + 12, sS2 + 12, 32);

    // block 3: 12->32, k9 s1 p4, pool 5/2, 111->54
    conv_popc_kernel<u32, 12, 32, 16, 9, 1, 4, 5, 2, 111, 54>
        <<<dim3(432, 2), 256>>>(bufP32, bufM, wp3, scales + 12, sS1 + 12, sS2 + 12);
    pack_stats_kernel<u32, 32, 54><<<432, 256>>>(bufM, sS1 + 12, sS2 + 12, scales + 12,
        g[2], b[2], 1.0 / (2048.0 * 54.0), bufP32, sS1 + 44, sS2 + 44, 64);

    // block 4: 32->64, k7 s1 p3, pool 4/2, 54->26
    conv_popc_kernel<u32, 32, 64, 16, 7, 1, 3, 4, 2, 54, 26>
        <<<dim3(208, 4), 256>>>(bufP32, bufM, wp4, scales + 44, sS1 + 44, sS2 + 44);
    pack_stats_kernel<u64, 64, 26><<<208, 256>>>(bufM, sS1 + 44, sS2 + 44, scales + 44,
        g[3], b[3], 1.0 / (2048.0 * 26.0), bufP, sS1 + 108, sS2 + 108, 64);

    // block 5: 64->64, k5 s1 p2, pool 2/2, 26->13
    conv_popc_kernel<u64, 64, 64, 16, 5, 1, 2, 2, 2, 26, 13>
        <<<dim3(104, 4), 256>>>(bufP, bufM, wp5, scales + 108, sS1 + 108, sS2 + 108);
    pack_stats_kernel<u64, 64, 13><<<104, 256>>>(bufM, sS1 + 108, sS2 + 108, scales + 108,
        g[4], b[4], 1.0 / (2048.0 * 13.0), bufP, sS1 + 172, sS2 + 172, 64);

    // block 6: 64->64, k3 s1 p1, pool 2/2, 13->6
    conv_popc_kernel<u64, 64, 64, 16, 3, 1, 1, 2, 2, 13, 6>
        <<<dim3(48, 4), 256>>>(bufP, bufM, wp6, scales + 172, sS1 + 172, sS2 + 172);
    pack_stats_kernel<u64, 64, 6><<<48, 256>>>(bufM, sS1 + 172, sS2 + 172, scales + 172,
        g[5], b[5], 1.0 / (2048.0 * 6.0), bufP, sS1 + 236, sS2 + 236, 72);

    // block 7: 64->72, k3 s1 p1, pool 2/2, 6->3
    conv_popc_kernel<u64, 64, 72, 24, 3, 1, 1, 2, 2, 6, 3>
        <<<dim3(24, 3), 256>>>(bufP, bufM, wp7, scales + 236, sS1 + 236, sS2 + 236);

    // FC (+ block7 BN recompute in-kernel)
    fc_bn_kernel<<<(NB * 5 + 255) / 256, 256>>>(bufM, bwfc, sS1 + 236, sS2 + 236,
                                                scales + 236, g[6], b[6], out);
}